// round 5
// baseline (speedup 1.0000x reference)
#include <cuda_runtime.h>
#include <cuda_bf16.h>
#include <cstdint>

// Problem constants
#define BDIM 4096
#define DDIM 4096
#define N2   8192
#define INVT 10.0f

// ---------------------------------------------------------------------------
// Scratch (device globals; no allocation allowed)
// ---------------------------------------------------------------------------
__device__ __nv_bfloat16  g_imb[(size_t)BDIM * DDIM];   // 32 MB
__device__ __nv_bfloat16  g_sb[(size_t)N2 * DDIM];      // 64 MB
__device__ float g_diag[BDIM];
__device__ float g_rowpart_m[32 * BDIM];
__device__ float g_rowpart_s[32 * BDIM];
__device__ float g_colpart_m[32 * BDIM];
__device__ float g_colpart_s[32 * BDIM];
__device__ float g_rowloss[BDIM];
__device__ float g_colloss[BDIM];

// ---------------------------------------------------------------------------
// PTX helpers (non-arch-specific; no tcgen05 — ptxas target is sm_103)
// ---------------------------------------------------------------------------
__device__ __forceinline__ uint32_t smem_u32(const void* p) {
    uint32_t a;
    asm("{ .reg .u64 t; cvta.to.shared.u64 t, %1; cvt.u32.u64 %0, t; }"
        : "=r"(a) : "l"(p));
    return a;
}
__device__ __forceinline__ void cpasync16(uint32_t dst, const void* src) {
    asm volatile("cp.async.cg.shared.global [%0], [%1], 16;"
                 :: "r"(dst), "l"(src) : "memory");
}
#define CP_COMMIT() asm volatile("cp.async.commit_group;" ::: "memory")
#define CP_WAIT2()  asm volatile("cp.async.wait_group 2;" ::: "memory")

__device__ __forceinline__ void ldsm4(uint32_t* r, uint32_t addr) {
    asm volatile("ldmatrix.sync.aligned.m8n8.x4.shared.b16 {%0,%1,%2,%3}, [%4];"
                 : "=r"(r[0]), "=r"(r[1]), "=r"(r[2]), "=r"(r[3]) : "r"(addr));
}
__device__ __forceinline__ void mma16816(float* d, const uint32_t* a,
                                         const uint32_t* b) {
    asm volatile(
        "mma.sync.aligned.m16n8k16.row.col.f32.bf16.bf16.f32 "
        "{%0,%1,%2,%3}, {%4,%5,%6,%7}, {%8,%9}, {%0,%1,%2,%3};"
        : "+f"(d[0]), "+f"(d[1]), "+f"(d[2]), "+f"(d[3])
        : "r"(a[0]), "r"(a[1]), "r"(a[2]), "r"(a[3]), "r"(b[0]), "r"(b[1]));
}

// Online lse helpers: state (m, s) with lse = m + log(s). Fixed-order -> deterministic.
__device__ __forceinline__ void lse_add(float& m, float& s, float x) {
    if (x > m) {
        float d = m - x;
        s = 1.f + ((d > -15.f) ? s * __expf(d) : 0.f);
        m = x;
    } else {
        float d = x - m;
        if (d > -15.f) s += __expf(d);
    }
}
__device__ __forceinline__ void lse_merge(float& m, float& s, float m2, float s2) {
    if (m2 > m) {
        float d = m - m2;
        s = s2 + ((d > -15.f) ? s * __expf(d) : 0.f);
        m = m2;
    } else {
        float d = m2 - m;
        s = s + ((d > -15.f) ? s2 * __expf(d) : 0.f);
    }
}

// ---------------------------------------------------------------------------
// fp32 -> bf16 conversion
// ---------------------------------------------------------------------------
__global__ void cvt_kernel(const float* __restrict__ src,
                           __nv_bfloat16* __restrict__ dst, int n4) {
    int i = blockIdx.x * blockDim.x + threadIdx.x;
    int stride = gridDim.x * blockDim.x;
    for (; i < n4; i += stride) {
        float4 f = ((const float4*)src)[i];
        __nv_bfloat162 lo = __floats2bfloat162_rn(f.x, f.y);
        __nv_bfloat162 hi = __floats2bfloat162_rn(f.z, f.w);
        uint2 u;
        u.x = *reinterpret_cast<uint32_t*>(&lo);
        u.y = *reinterpret_cast<uint32_t*>(&hi);
        ((uint2*)dst)[i] = u;
    }
}

// ---------------------------------------------------------------------------
// diag[i] = 0.5*sl[i,i] + 0.5*dot(im[i,:], s[i,:])   (fp32 exact)
// ---------------------------------------------------------------------------
__global__ void diag_kernel(const float* __restrict__ im,
                            const float* __restrict__ s,
                            const float* __restrict__ sl) {
    int i = blockIdx.x;
    const float4* a = (const float4*)(im + (size_t)i * DDIM);
    const float4* b = (const float4*)(s  + (size_t)i * DDIM);
    float sum = 0.f;
    for (int k = threadIdx.x; k < DDIM / 4; k += 256) {
        float4 av = a[k], bv = b[k];
        sum += av.x * bv.x + av.y * bv.y + av.z * bv.z + av.w * bv.w;
    }
    __shared__ float red[256];
    red[threadIdx.x] = sum;
    __syncthreads();
    for (int off = 128; off > 0; off >>= 1) {
        if (threadIdx.x < off) red[threadIdx.x] += red[threadIdx.x + off];
        __syncthreads();
    }
    if (threadIdx.x == 0)
        g_diag[i] = 0.5f * sl[(size_t)i * N2 + i] + 0.5f * red[0];
}

// ---------------------------------------------------------------------------
// Fused bf16 mma.sync GEMM + masked-lse partial reductions.
// CTA 128x256, K-chunk 64, 4 cp.async stages, 256 threads (8 warps, 2x4).
// No sim matrix is materialized: each CTA emits per-row and per-col (m,s)
// logsumexp partials of  x = INVT * masked(0.5*SL + 0.5*im@s^T).
// ---------------------------------------------------------------------------
#define BM 128
#define BN 256
#define BK 64
#define RS 72                        // halves per padded smem row (144 B)
#define STAGES 4
#define A_HALVES (BM * RS)           // 9216
#define B_HALVES (BN * RS)           // 18432
#define STG_HALVES (A_HALVES + B_HALVES)
#define SMEM_GEMM (STAGES * STG_HALVES * 2)   // 221184 B
#define NKIT (DDIM / BK)             // 64

__global__ __launch_bounds__(256, 1)
void gemm_fused(const __nv_bfloat16* __restrict__ A,   // [4096][4096]
                const __nv_bfloat16* __restrict__ B,   // [8192][4096]
                const float* __restrict__ SL) {
    extern __shared__ __align__(1024) __nv_bfloat16 sm[];
    const uint32_t sbase = smem_u32(sm);
    const int tid   = threadIdx.x;
    const int lane  = tid & 31;
    const int wid   = tid >> 5;
    const int warpM = wid >> 2;     // 0..1
    const int warpN = wid & 3;      // 0..3
    const int bx = blockIdx.x;      // 0..31 (N tiles)
    const int by = blockIdx.y;      // 0..31 (M tiles)
    const int m0 = by * BM;
    const int n0 = bx * BN;

    // cp.async loader: 16B chunks. A: 1024 chunks/stage, B: 2048.
    const int lrow = tid >> 3;           // 0..31
    const int lcol = (tid & 7) * 8;      // halves

    float acc[4][8][4];
    #pragma unroll
    for (int mf = 0; mf < 4; mf++)
        #pragma unroll
        for (int nf = 0; nf < 8; nf++)
            #pragma unroll
            for (int q = 0; q < 4; q++) acc[mf][nf][q] = 0.f;

    // Prologue: stages 0..2
    #pragma unroll
    for (int st = 0; st < STAGES - 1; st++) {
        const int k0 = st * BK;
        uint32_t sA = sbase + st * STG_HALVES * 2;
        uint32_t sB = sA + A_HALVES * 2;
        #pragma unroll
        for (int i = 0; i < 4; i++) {
            int row = lrow + i * 32;
            cpasync16(sA + (row * RS + lcol) * 2,
                      A + (size_t)(m0 + row) * DDIM + k0 + lcol);
        }
        #pragma unroll
        for (int i = 0; i < 8; i++) {
            int row = lrow + i * 32;
            cpasync16(sB + (row * RS + lcol) * 2,
                      B + (size_t)(n0 + row) * DDIM + k0 + lcol);
        }
        CP_COMMIT();
    }

    #pragma unroll 1
    for (int it = 0; it < NKIT; it++) {
        CP_WAIT2();
        __syncthreads();

        if (it + 3 < NKIT) {
            const int st = (it + 3) & 3;
            const int k0 = (it + 3) * BK;
            uint32_t sA = sbase + st * STG_HALVES * 2;
            uint32_t sB = sA + A_HALVES * 2;
            #pragma unroll
            for (int i = 0; i < 4; i++) {
                int row = lrow + i * 32;
                cpasync16(sA + (row * RS + lcol) * 2,
                          A + (size_t)(m0 + row) * DDIM + k0 + lcol);
            }
            #pragma unroll
            for (int i = 0; i < 8; i++) {
                int row = lrow + i * 32;
                cpasync16(sB + (row * RS + lcol) * 2,
                          B + (size_t)(n0 + row) * DDIM + k0 + lcol);
            }
        }
        CP_COMMIT();

        uint32_t sA = sbase + (it & 3) * STG_HALVES * 2;
        uint32_t sB = sA + A_HALVES * 2;
        #pragma unroll
        for (int s = 0; s < 4; s++) {       // four k16 steps in BK=64
            uint32_t a[4][4], b[4][4];
            #pragma unroll
            for (int mf = 0; mf < 4; mf++) {
                int row = warpM * 64 + mf * 16 + (lane & 15);
                int ko  = s * 16 + (lane >> 4) * 8;
                ldsm4(a[mf], sA + (row * RS + ko) * 2);
            }
            const int q = lane >> 3;
            #pragma unroll
            for (int nf2 = 0; nf2 < 4; nf2++) {
                int row = warpN * 64 + nf2 * 16 + (q >> 1) * 8 + (lane & 7);
                int ko  = s * 16 + (q & 1) * 8;
                ldsm4(b[nf2], sB + (row * RS + ko) * 2);
            }
            #pragma unroll
            for (int mf = 0; mf < 4; mf++)
                #pragma unroll
                for (int nf = 0; nf < 8; nf++)
                    mma16816(acc[mf][nf], a[mf], b[nf >> 1] + (nf & 1) * 2);
        }
    }

    // =======================================================================
    // Fused epilogue. Thread's element (mf,nf,h,q2):
    //   row = warpM*64 + mf*16 + h*8 + (lane>>2)
    //   col = warpN*64 + nf*8 + (lane&3)*2 + q2
    // =======================================================================
    const bool second = (n0 >= BDIM);

    // diag for my 8 rows (masking)
    float dg[8];
    #pragma unroll
    for (int r8 = 0; r8 < 8; r8++)
        dg[r8] = g_diag[m0 + warpM * 64 + (r8 >> 1) * 16 + (r8 & 1) * 8 + (lane >> 2)];

    // Transform acc in place: x = INVT * masked(0.5*SL + 0.5*acc)
    #pragma unroll
    for (int mf = 0; mf < 4; mf++) {
        #pragma unroll
        for (int h = 0; h < 2; h++) {
            int rowg = m0 + warpM * 64 + mf * 16 + h * 8 + (lane >> 2);
            size_t rbase = (size_t)rowg * N2 + n0 + warpN * 64 + (lane & 3) * 2;
            float d = dg[mf * 2 + h];
            #pragma unroll
            for (int nf = 0; nf < 8; nf++) {
                float2 sl2 = *(const float2*)(SL + rbase + nf * 8);
                float v0 = 0.5f * sl2.x + 0.5f * acc[mf][nf][h * 2 + 0];
                float v1 = 0.5f * sl2.y + 0.5f * acc[mf][nf][h * 2 + 1];
                if (second) {
                    if (v0 > d) v0 = 0.f;
                    if (v1 > d) v1 = 0.f;
                }
                acc[mf][nf][h * 2 + 0] = v0 * INVT;
                acc[mf][nf][h * 2 + 1] = v1 * INVT;
            }
        }
    }

    // ---- Row partials: per thread 8 rows x 16 cols ----
    float rm[8], rs[8];
    #pragma unroll
    for (int r8 = 0; r8 < 8; r8++) {
        int mf = r8 >> 1, h = r8 & 1;
        float m = -1e30f, s = 0.f;
        #pragma unroll
        for (int nf = 0; nf < 8; nf++) {
            lse_add(m, s, acc[mf][nf][h * 2 + 0]);
            lse_add(m, s, acc[mf][nf][h * 2 + 1]);
        }
        // merge across the 4 lanes sharing this row (lane&3 varies)
        #pragma unroll
        for (int d = 1; d <= 2; d <<= 1) {
            float om = __shfl_xor_sync(0xffffffffu, m, d);
            float os = __shfl_xor_sync(0xffffffffu, s, d);
            lse_merge(m, s, om, os);
        }
        rm[r8] = m; rs[r8] = s;
    }

    // ---- Col partials: per thread 16 cols x 8 rows ----
    float cm[16], cs[16];
    #pragma unroll
    for (int nf = 0; nf < 8; nf++) {
        #pragma unroll
        for (int q2 = 0; q2 < 2; q2++) {
            float m = -1e30f, s = 0.f;
            #pragma unroll
            for (int mf = 0; mf < 4; mf++) {
                lse_add(m, s, acc[mf][nf][0 * 2 + q2]);
                lse_add(m, s, acc[mf][nf][1 * 2 + q2]);
            }
            // merge across the 8 lanes sharing these cols (lane>>2 varies)
            #pragma unroll
            for (int d = 4; d <= 16; d <<= 1) {
                float om = __shfl_xor_sync(0xffffffffu, m, d);
                float os = __shfl_xor_sync(0xffffffffu, s, d);
                lse_merge(m, s, om, os);
            }
            cm[nf * 2 + q2] = m; cs[nf * 2 + q2] = s;
        }
    }

    // ---- smem cross-warp combines (fixed order -> deterministic) ----
    __syncthreads();                 // mainloop smem reads all done
    float* red_m = (float*)sm;       // [128]
    float* red_s = red_m + 128;      // [128]
    float* col_m = red_s + 128;      // [256]
    float* col_s = col_m + 256;      // [256]

    // rows: combine over warpN = 0..3
    #pragma unroll 1
    for (int w = 0; w < 4; w++) {
        if (warpN == w && (lane & 3) == 0) {
            #pragma unroll
            for (int r8 = 0; r8 < 8; r8++) {
                int r = warpM * 64 + (r8 >> 1) * 16 + (r8 & 1) * 8 + (lane >> 2);
                if (w == 0) { red_m[r] = rm[r8]; red_s[r] = rs[r8]; }
                else {
                    float m = red_m[r], s = red_s[r];
                    lse_merge(m, s, rm[r8], rs[r8]);
                    red_m[r] = m; red_s[r] = s;
                }
            }
        }
        __syncthreads();
    }

    // cols: combine over warpM = 0..1
    #pragma unroll 1
    for (int w = 0; w < 2; w++) {
        if (warpM == w && (lane >> 2) == 0) {
            #pragma unroll
            for (int nf = 0; nf < 8; nf++) {
                #pragma unroll
                for (int q2 = 0; q2 < 2; q2++) {
                    int c = warpN * 64 + nf * 8 + (lane & 3) * 2 + q2;
                    if (w == 0) { col_m[c] = cm[nf * 2 + q2]; col_s[c] = cs[nf * 2 + q2]; }
                    else {
                        float m = col_m[c], s = col_s[c];
                        lse_merge(m, s, cm[nf * 2 + q2], cs[nf * 2 + q2]);
                        col_m[c] = m; col_s[c] = s;
                    }
                }
            }
        }
        __syncthreads();
    }

    // ---- global partial writes ----
    if (tid < 128) {
        g_rowpart_m[bx * BDIM + m0 + tid] = red_m[tid];
        g_rowpart_s[bx * BDIM + m0 + tid] = red_s[tid];
    }
    if (!second) {   // bx < 16: first-half columns feed the t2i loss
        g_colpart_m[by * BDIM + n0 + tid] = col_m[tid];
        g_colpart_s[by * BDIM + n0 + tid] = col_s[tid];
    }
}

// ---------------------------------------------------------------------------
// Combine 32 partials per row / per col (fixed order) -> per-element losses
// ---------------------------------------------------------------------------
__global__ void combine_kernel() {
    int j = blockIdx.x * 128 + threadIdx.x;   // 0..4095
    float dgt = g_diag[j] * INVT;

    float m = -1e30f, s = 0.f;
    #pragma unroll 1
    for (int c = 0; c < 32; c++)
        lse_merge(m, s, g_rowpart_m[c * BDIM + j], g_rowpart_s[c * BDIM + j]);
    g_rowloss[j] = m + __logf(s) - dgt;

    m = -1e30f; s = 0.f;
    #pragma unroll 1
    for (int c = 0; c < 32; c++)
        lse_merge(m, s, g_colpart_m[c * BDIM + j], g_colpart_s[c * BDIM + j]);
    g_colloss[j] = m + __logf(s) - dgt;
}

__global__ void final_kernel(float* __restrict__ out) {
    int t = threadIdx.x;
    float sum = 0.f;
    for (int i = t; i < BDIM; i += 1024)
        sum += g_rowloss[i] + g_colloss[i];
    __shared__ float red[1024];
    red[t] = sum;
    __syncthreads();
    for (int off = 512; off > 0; off >>= 1) {
        if (t < off) red[t] += red[t + off];
        __syncthreads();
    }
    if (t == 0) out[0] = red[0] * (1.0f / (float)BDIM);
}

// ---------------------------------------------------------------------------
extern "C" void kernel_launch(void* const* d_in, const int* in_sizes, int n_in,
                              void* d_out, int out_size) {
    const float* im = (const float*)d_in[0];   // [4096, 4096]
    const float* s  = (const float*)d_in[1];   // [8192, 4096]
    const float* sl = (const float*)d_in[2];   // [4096, 8192]
    float* out = (float*)d_out;

    __nv_bfloat16 *imb = nullptr, *sbm = nullptr;
    cudaGetSymbolAddress((void**)&imb, g_imb);
    cudaGetSymbolAddress((void**)&sbm, g_sb);

    cvt_kernel<<<4096, 256>>>(im, imb, (BDIM * DDIM) / 4);
    cvt_kernel<<<8192, 256>>>(s,  sbm, (N2 * DDIM) / 4);
    diag_kernel<<<BDIM, 256>>>(im, s, sl);

    cudaFuncSetAttribute(gemm_fused, cudaFuncAttributeMaxDynamicSharedMemorySize,
                         SMEM_GEMM);
    dim3 gg(N2 / BN, BDIM / BM);   // (32, 32)
    gemm_fused<<<gg, 256, SMEM_GEMM>>>(imb, sbm, sl);

    combine_kernel<<<32, 128>>>();
    final_kernel<<<1, 1024>>>(out);
}